// round 2
// baseline (speedup 1.0000x reference)
#include <cuda_runtime.h>
#include <cstdint>

// SpikeFP8MulToFP32:
//   A, B: [N, 8] float 0/1 bit-vectors of fp8 e4m3 (order S,E3..E0,M2,M1,M0)
//   out : [N, 32] float 0/1 bit-vector of fp32(A_val * B_val), MSB (sign) first.
//
// Streaming kernel: 256 MB in, 512 MB out, zero reuse -> pure HBM roofline.
// R2 changes vs R1 (115.9us, DRAM 78.8%):
//   - 256-bit LDG/STG (sm_100a v8.b32): one load per 32B input row, warp
//     stores cover 1KB (8 full lines) per instruction -> half the L1
//     wavefronts and half the ld/st instruction count
//   - 512 rows per block (2 rows/thread): more bytes in flight per thread,
//     half the __syncthreads

#define ROWS_PER_BLOCK 512
#define THREADS 256

static __device__ __forceinline__ void ldg_v8_cs(const uint32_t* p, uint32_t r[8]) {
    asm volatile("ld.global.cs.v8.b32 {%0,%1,%2,%3,%4,%5,%6,%7}, [%8];"
                 : "=r"(r[0]), "=r"(r[1]), "=r"(r[2]), "=r"(r[3]),
                   "=r"(r[4]), "=r"(r[5]), "=r"(r[6]), "=r"(r[7])
                 : "l"(p));
}

static __device__ __forceinline__ void stg_v8_cs(uint32_t* p, const uint32_t v[8]) {
    asm volatile("st.global.cs.v8.b32 [%0], {%1,%2,%3,%4,%5,%6,%7,%8};"
                 :: "l"(p),
                    "r"(v[0]), "r"(v[1]), "r"(v[2]), "r"(v[3]),
                    "r"(v[4]), "r"(v[5]), "r"(v[6]), "r"(v[7]));
}

static __device__ __forceinline__ uint32_t bit_of(uint32_t w) {
    // inputs are exactly 0.0f (0x00000000) or 1.0f (0x3F800000): test bit 23
    return (w >> 23) & 1u;
}

static __device__ __forceinline__ uint32_t decode_mul_bits(const uint32_t a[8],
                                                           const uint32_t b[8]) {
    // decode e4m3: normal (8+m)*2^(e-10), subnormal m*2^-9; sign ORed so
    // -0.0 products keep their sign bit (reference bitcasts the fp32 result)
    uint32_t sa = bit_of(a[0]);
    uint32_t ea = (bit_of(a[1]) << 3) | (bit_of(a[2]) << 2) | (bit_of(a[3]) << 1) | bit_of(a[4]);
    uint32_t ma = (bit_of(a[5]) << 2) | (bit_of(a[6]) << 1) | bit_of(a[7]);
    uint32_t Ma = ea ? (8u + ma) : ma;
    int      Ea = ea ? ((int)ea - 10) : -9;
    float va = (float)(int)Ma * __int_as_float((Ea + 127) << 23);
    va = __uint_as_float(__float_as_uint(va) | (sa << 31));

    uint32_t sb = bit_of(b[0]);
    uint32_t eb = (bit_of(b[1]) << 3) | (bit_of(b[2]) << 2) | (bit_of(b[3]) << 1) | bit_of(b[4]);
    uint32_t mb = (bit_of(b[5]) << 2) | (bit_of(b[6]) << 1) | bit_of(b[7]);
    uint32_t Mb = eb ? (8u + mb) : mb;
    int      Eb = eb ? ((int)eb - 10) : -9;
    float vb = (float)(int)Mb * __int_as_float((Eb + 127) << 23);
    vb = __uint_as_float(__float_as_uint(vb) | (sb << 31));

    return __float_as_uint(va * vb);   // exact in fp32; IEEE sign-of-zero
}

__global__ void __launch_bounds__(THREADS)
spike_fp8_mul_kernel(const uint32_t* __restrict__ A,
                     const uint32_t* __restrict__ B,
                     uint32_t* __restrict__ out,
                     int nrows) {
    __shared__ uint32_t sh[ROWS_PER_BLOCK];

    const int tid  = threadIdx.x;
    const int base = blockIdx.x * ROWS_PER_BLOCK;

    // ---- load + decode: 2 rows per thread, one 256-bit load per row/operand
    uint32_t p0 = 0, p1 = 0;
    const int r0 = base + tid;
    const int r1 = base + THREADS + tid;
    if (r0 < nrows) {
        uint32_t a[8], b[8];
        ldg_v8_cs(A + (size_t)r0 * 8, a);
        ldg_v8_cs(B + (size_t)r0 * 8, b);
        p0 = decode_mul_bits(a, b);
    }
    if (r1 < nrows) {
        uint32_t a[8], b[8];
        ldg_v8_cs(A + (size_t)r1 * 8, a);
        ldg_v8_cs(B + (size_t)r1 * 8, b);
        p1 = decode_mul_bits(a, b);
    }
    sh[tid] = p0;
    sh[THREADS + tid] = p1;
    __syncthreads();

    // ---- store: block tile = 512 rows * 32 floats = 2048 x 32B (v8) stores.
    // v8 chunk q covers output floats [8q .. 8q+7]: row = q>>2, byte group
    // g = q&3 holds product bits [31-8g .. 24-8g], MSB-first within group.
    const int rows_left = nrows - base;                       // > 0
    const int q_limit   = rows_left >= ROWS_PER_BLOCK ? ROWS_PER_BLOCK * 4
                                                      : rows_left * 4;
    uint32_t* blk_out = out + (size_t)base * 32;
    const int g_shift = 24 - ((tid & 3) << 3);                // loop-invariant

#pragma unroll
    for (int k = 0; k < (ROWS_PER_BLOCK * 4) / THREADS; k++) {
        int q = k * THREADS + tid;
        if (q < q_limit) {
            uint32_t t = sh[q >> 2] >> g_shift;               // 4-lane broadcast
            uint32_t v[8];
#pragma unroll
            for (int j = 0; j < 8; j++)
                v[j] = ((t >> (7 - j)) & 1u) * 0x3F800000u;
            stg_v8_cs(blk_out + (size_t)q * 8, v);
        }
    }
}

extern "C" void kernel_launch(void* const* d_in, const int* in_sizes, int n_in,
                              void* d_out, int out_size) {
    const uint32_t* A = (const uint32_t*)d_in[0];
    const uint32_t* B = (const uint32_t*)d_in[1];
    uint32_t* out = (uint32_t*)d_out;

    int nrows = in_sizes[0] / 8;
    int blocks = (nrows + ROWS_PER_BLOCK - 1) / ROWS_PER_BLOCK;
    spike_fp8_mul_kernel<<<blocks, THREADS>>>(A, B, out, nrows);
}